// round 16
// baseline (speedup 1.0000x reference)
#include <cuda_runtime.h>
#include <cuda_fp16.h>
#include <math.h>
#include <stdint.h>

// Problem constants
#define Bv 2
#define Tv 8
#define Nv 576
#define Cv 1024
#define Hv 16
#define HDv 64
#define TNv (Tv * Nv)       // 4608
#define Mrows (Bv * TNv)    // 9216
#define CW (Cv / 2)         // 512 uint words per token row

// Scratch (device globals — no runtime allocation allowed)
__device__ __half g_qh[(size_t)Mrows * Cv];
__device__ __half g_kh[(size_t)Mrows * Cv];
__device__ __half g_vh[(size_t)Mrows * Cv];
__device__ __half g_oh[(size_t)Mrows * Cv];
__device__ __half g_imgh[(size_t)Mrows * Cv];
__device__ __half g_wqh[(size_t)Cv * Cv];
__device__ __half g_wkh[(size_t)Cv * Cv];
__device__ __half g_wvh[(size_t)Cv * Cv];
__device__ __half g_woh[(size_t)Cv * Cv];

// ---------------------------------------------------------------------------
// helpers
// ---------------------------------------------------------------------------
__device__ __forceinline__ unsigned f2h2(float lo, float hi) {
    __half2 h = __floats2half2_rn(lo, hi);
    return *(unsigned*)&h;
}
__device__ __forceinline__ unsigned h2lows(unsigned a, unsigned b) {
    unsigned r;
    asm("prmt.b32 %0, %1, %2, 0x5410;" : "=r"(r) : "r"(a), "r"(b));
    return r;
}
__device__ __forceinline__ unsigned h2highs(unsigned a, unsigned b) {
    unsigned r;
    asm("prmt.b32 %0, %1, %2, 0x7632;" : "=r"(r) : "r"(a), "r"(b));
    return r;
}
__device__ __forceinline__ void mma16(float d[4], const unsigned a[4],
                                      const unsigned b[2]) {
    asm volatile(
        "mma.sync.aligned.m16n8k16.row.col.f32.f16.f16.f32 "
        "{%0,%1,%2,%3},{%4,%5,%6,%7},{%8,%9},{%0,%1,%2,%3};"
        : "+f"(d[0]), "+f"(d[1]), "+f"(d[2]), "+f"(d[3])
        : "r"(a[0]), "r"(a[1]), "r"(a[2]), "r"(a[3]), "r"(b[0]), "r"(b[1]));
}
__device__ __forceinline__ uint32_t smem_u32(const void* p) {
    uint32_t a;
    asm("{ .reg .u64 t; cvta.to.shared.u64 t, %1; cvt.u32.u64 %0, t; }"
        : "=r"(a) : "l"(p));
    return a;
}
__device__ __forceinline__ void ldsm4(unsigned& r0, unsigned& r1,
                                      unsigned& r2, unsigned& r3,
                                      uint32_t addr) {
    asm volatile(
        "ldmatrix.sync.aligned.m8n8.x4.shared.b16 {%0,%1,%2,%3}, [%4];"
        : "=r"(r0), "=r"(r1), "=r"(r2), "=r"(r3) : "r"(addr));
}

// ---------------------------------------------------------------------------
// Merged fp32 -> fp16 conversion pre-pass (img + 4 weights), 8 elems/thread
// ---------------------------------------------------------------------------
#define IMG8 ((int)((size_t)Mrows * Cv / 8))   // 1179648
#define W8   ((int)((size_t)Cv * Cv / 8))      // 131072
#define TOT8 (IMG8 + 4 * W8)                   // 1703936

__global__ __launch_bounds__(256) void cvt_all(
    const float* __restrict__ img, const float* __restrict__ wq,
    const float* __restrict__ wk, const float* __restrict__ wv,
    const float* __restrict__ wo)
{
    int i = blockIdx.x * blockDim.x + threadIdx.x;
    if (i >= TOT8) return;
    const float* s;
    __half* d;
    if (i < IMG8) {
        s = img + (size_t)i * 8;
        d = g_imgh + (size_t)i * 8;
    } else {
        int j = i - IMG8;
        int wsel = j / W8, r = j % W8;
        const float* ws = (wsel == 0) ? wq : (wsel == 1) ? wk
                         : (wsel == 2) ? wv : wo;
        __half* wd = (wsel == 0) ? g_wqh : (wsel == 1) ? g_wkh
                    : (wsel == 2) ? g_wvh : g_woh;
        s = ws + (size_t)r * 8;
        d = wd + (size_t)r * 8;
    }
    const float4* sp = (const float4*)s;
    float4 a = sp[0], b2 = sp[1];
    uint4 o;
    o.x = f2h2(a.x, a.y);  o.y = f2h2(a.z, a.w);
    o.z = f2h2(b2.x, b2.y); o.w = f2h2(b2.z, b2.w);
    *(uint4*)d = o;
}

// ---------------------------------------------------------------------------
// Projection GEMM (A half, W half): out = half( rope?( scale * A@W^T ) )
// 512 threads = 16 warps (4m x 4n), 32x32 warp tile, 32-reg accumulator.
// ROW-MAJOR smem [row][k] (16 words/row), swizzle group' = g ^ ((row>>1)&3);
// fragments via ldmatrix.x4 (validated round 15). 16 resident warps/SM.
// ---------------------------------------------------------------------------
__global__ __launch_bounds__(512) void gemm_proj(
    const __half* __restrict__ Ah, const __half* __restrict__ Wh,
    __half* __restrict__ Out,
    const float* __restrict__ fcos, const float* __restrict__ fsin,
    float scale)
{
    __shared__ unsigned As[128 * 16];
    __shared__ unsigned Bs[128 * 16];

    const int t = threadIdx.x;
    const int lane = t & 31;
    const int w = t >> 5;                  // 0..15
    const int gid = lane >> 2, tig = lane & 3;
    const int wm = (w >> 2) * 32, wn = (w & 3) * 32;
    const int m0 = blockIdx.y * 128, n0 = blockIdx.x * 128;

    // loader: one row of A + one row of B per thread
    const int row0 = t >> 2;               // 0..127
    const int kg = t & 3;
    const unsigned* Ap = (const unsigned*)Ah + (size_t)(m0 + row0) * CW + kg * 4;
    const unsigned* Wp = (const unsigned*)Wh + (size_t)(n0 + row0) * CW + kg * 4;

    const int sts = row0 * 16 + (kg ^ ((row0 >> 1) & 3)) * 4;

    // LDSM per-lane bases (loop-invariant)
    const uint32_t sbA = smem_u32(As), sbB = smem_u32(Bs);
    const int aRowL = ((lane >> 3) & 1) * 8 + (lane & 7);
    const int aKsel = lane >> 4;              // 0/1
    const int bRowL = (lane >> 4) * 8 + (lane & 7);
    const int bKsel = (lane >> 3) & 1;
    uint32_t baseA[2]; int swzA[2];
#pragma unroll
    for (int mt = 0; mt < 2; mt++) {
        int r = wm + mt * 16 + aRowL;
        baseA[mt] = sbA + (uint32_t)(r * 16) * 4;
        swzA[mt] = (r >> 1) & 3;
    }
    uint32_t baseB[2]; int swzB[2];
#pragma unroll
    for (int np = 0; np < 2; np++) {
        int r = wn + np * 16 + bRowL;
        baseB[np] = sbB + (uint32_t)(r * 16) * 4;
        swzB[np] = (r >> 1) & 3;
    }

    float acc[2][4][4];
#pragma unroll
    for (int mt = 0; mt < 2; mt++)
#pragma unroll
        for (int nt = 0; nt < 4; nt++)
#pragma unroll
            for (int r = 0; r < 4; r++) acc[mt][nt][r] = 0.0f;

    uint4 xa = *(const uint4*)Ap;
    uint4 za = *(const uint4*)Wp;

    for (int ch = 0; ch < 32; ch++) {
        __syncthreads();
        *(uint4*)(As + sts) = xa;
        *(uint4*)(Bs + sts) = za;
        __syncthreads();
        if (ch + 1 < 32) {
            const int kc = (ch + 1) * 16;
            xa = *(const uint4*)(Ap + kc);
            za = *(const uint4*)(Wp + kc);
        }
#pragma unroll
        for (int s = 0; s < 2; s++) {
            unsigned a[2][4], bb[4][2];
            const int gA = s * 2 + aKsel;
            const int gB = s * 2 + bKsel;
#pragma unroll
            for (int mt = 0; mt < 2; mt++)
                ldsm4(a[mt][0], a[mt][1], a[mt][2], a[mt][3],
                      baseA[mt] + (uint32_t)((gA ^ swzA[mt]) << 4));
#pragma unroll
            for (int np = 0; np < 2; np++) {
                unsigned r0, r1, r2, r3;
                ldsm4(r0, r1, r2, r3,
                      baseB[np] + (uint32_t)((gB ^ swzB[np]) << 4));
                bb[2 * np][0] = r0;  bb[2 * np][1] = r1;
                bb[2 * np + 1][0] = r2;  bb[2 * np + 1][1] = r3;
            }
#pragma unroll
            for (int mt = 0; mt < 2; mt++)
#pragma unroll
                for (int nt = 0; nt < 4; nt++)
                    mma16(acc[mt][nt], a[mt], bb[nt]);
        }
    }

    const bool rope = (fcos != nullptr);
#pragma unroll
    for (int mt = 0; mt < 2; mt++) {
        const int r = m0 + wm + mt * 16 + gid;
        const int r8 = r + 8;
        const int s_lo = (r  >= TNv) ? r  - TNv : r;
        const int s_hi = (r8 >= TNv) ? r8 - TNv : r8;
#pragma unroll
        for (int nt = 0; nt < 4; nt++) {
            const int c = n0 + wn + nt * 8 + tig * 2;
            float a0 = acc[mt][nt][0] * scale;
            float a1 = acc[mt][nt][1] * scale;
            float a2 = acc[mt][nt][2] * scale;
            float a3 = acc[mt][nt][3] * scale;
            if (rope) {
                const int d = c & 63;
                float2 cl = *(const float2*)(fcos + (size_t)s_lo * HDv + d);
                float2 sl = *(const float2*)(fsin + (size_t)s_lo * HDv + d);
                float2 chh = *(const float2*)(fcos + (size_t)s_hi * HDv + d);
                float2 sh = *(const float2*)(fsin + (size_t)s_hi * HDv + d);
                float y0 = a0 * cl.x - a1 * sl.x;
                float y1 = a1 * cl.y + a0 * sl.y;
                float y2 = a2 * chh.x - a3 * sh.x;
                float y3 = a3 * chh.y + a2 * sh.y;
                a0 = y0; a1 = y1; a2 = y2; a3 = y3;
            }
            *(unsigned*)(Out + (size_t)r  * Cv + c) = f2h2(a0, a1);
            *(unsigned*)(Out + (size_t)r8 * Cv + c) = f2h2(a2, a3);
        }
    }
}

// ---------------------------------------------------------------------------
// Output GEMM (A half, W half): out fp32 = A@W^T + bias. Same 512-thr scheme.
// ---------------------------------------------------------------------------
__global__ __launch_bounds__(512) void gemm_out(
    const __half* __restrict__ Ah, const __half* __restrict__ Wh,
    float* __restrict__ Cout, const float* __restrict__ bias)
{
    __shared__ unsigned As[128 * 16];
    __shared__ unsigned Bs[128 * 16];

    const int t = threadIdx.x;
    const int lane = t & 31;
    const int w = t >> 5;
    const int gid = lane >> 2, tig = lane & 3;
    const int wm = (w >> 2) * 32, wn = (w & 3) * 32;
    const int m0 = blockIdx.y * 128, n0 = blockIdx.x * 128;

    const int row0 = t >> 2;
    const int kg = t & 3;
    const unsigned* Ap = (const unsigned*)Ah + (size_t)(m0 + row0) * CW + kg * 4;
    const unsigned* Wp = (const unsigned*)Wh + (size_t)(n0 + row0) * CW + kg * 4;

    const int sts = row0 * 16 + (kg ^ ((row0 >> 1) & 3)) * 4;

    const uint32_t sbA = smem_u32(As), sbB = smem_u32(Bs);
    const int aRowL = ((lane >> 3) & 1) * 8 + (lane & 7);
    const int aKsel = lane >> 4;
    const int bRowL = (lane >> 4) * 8 + (lane & 7);
    const int bKsel = (lane >> 3) & 1;
    uint32_t baseA[2]; int swzA[2];
#pragma unroll
    for (int mt = 0; mt < 2; mt++) {
        int r = wm + mt * 16 + aRowL;
        baseA[mt] = sbA + (uint32_t)(r * 16) * 4;
        swzA[mt] = (r >> 1) & 3;
    }
    uint32_t baseB[2]; int swzB[2];
#pragma unroll
    for (int np = 0; np < 2; np++) {
        int r = wn + np * 16 + bRowL;
        baseB[np] = sbB + (uint32_t)(r * 16) * 4;
        swzB[np] = (r >> 1) & 3;
    }

    float acc[2][4][4];
#pragma unroll
    for (int mt = 0; mt < 2; mt++)
#pragma unroll
        for (int nt = 0; nt < 4; nt++)
#pragma unroll
            for (int r = 0; r < 4; r++) acc[mt][nt][r] = 0.0f;

    uint4 xa = *(const uint4*)Ap;
    uint4 za = *(const uint4*)Wp;

    for (int ch = 0; ch < 32; ch++) {
        __syncthreads();
        *(uint4*)(As + sts) = xa;
        *(uint4*)(Bs + sts) = za;
        __syncthreads();
        if (ch + 1 < 32) {
            const int kc = (ch + 1) * 16;
            xa = *(const uint4*)(Ap + kc);
            za = *(const uint4*)(Wp + kc);
        }
#pragma unroll
        for (int s = 0; s < 2; s++) {
            unsigned a[2][4], bb[4][2];
            const int gA = s * 2 + aKsel;
            const int gB = s * 2 + bKsel;
#pragma unroll
            for (int mt = 0; mt < 2; mt++)
                ldsm4(a[mt][0], a[mt][1], a[mt][2], a[mt][3],
                      baseA[mt] + (uint32_t)((gA ^ swzA[mt]) << 4));
#pragma unroll
            for (int np = 0; np < 2; np++) {
                unsigned r0, r1, r2, r3;
                ldsm4(r0, r1, r2, r3,
                      baseB[np] + (uint32_t)((gB ^ swzB[np]) << 4));
                bb[2 * np][0] = r0;  bb[2 * np][1] = r1;
                bb[2 * np + 1][0] = r2;  bb[2 * np + 1][1] = r3;
            }
#pragma unroll
            for (int mt = 0; mt < 2; mt++)
#pragma unroll
                for (int nt = 0; nt < 4; nt++)
                    mma16(acc[mt][nt], a[mt], bb[nt]);
        }
    }

#pragma unroll
    for (int mt = 0; mt < 2; mt++) {
        int r = m0 + wm + mt * 16 + gid;
#pragma unroll
        for (int nt = 0; nt < 4; nt++) {
            int c = n0 + wn + nt * 8 + tig * 2;
            float b0v = bias[c], b1v = bias[c + 1];
            float2 v0, v1;
            v0.x = acc[mt][nt][0] + b0v;
            v0.y = acc[mt][nt][1] + b1v;
            v1.x = acc[mt][nt][2] + b0v;
            v1.y = acc[mt][nt][3] + b1v;
            *(float2*)(Cout + (size_t)r * Cv + c) = v0;
            *(float2*)(Cout + (size_t)(r + 8) * Cv + c) = v1;
        }
    }
}

// ---------------------------------------------------------------------------
// Flash attention, fp16 (round-11/15 version, UNCHANGED).
// Buffer layout (uint words): [Ks0|Vs0|Ks1|Vs1|Ps|red|Mrow|Lrow|Arow]
// ---------------------------------------------------------------------------
#define AKS0 0
#define AVS0 2304
#define AKS1 4608
#define AVS1 6912
#define APS  9216
#define ARED 11520
#define AMR  11776
#define ALR  11840
#define AAR  11904
#define ATTN_SMEM_WORDS 11968

__global__ __launch_bounds__(256) void attn_fp16()
{
    extern __shared__ unsigned usm[];
    unsigned* Ps = usm + APS;
    float* red  = (float*)(usm + ARED);
    float* Mrow = (float*)(usm + AMR);
    float* Lrow = (float*)(usm + ALR);
    float* Arow = (float*)(usm + AAR);

    const int bx = blockIdx.x;
    const int nb = bx % 9;
    const int tt = (bx / 9) % Tv;
    const int hh = (bx / (9 * Tv)) % Hv;
    const int b  = bx / (9 * Tv * Hv);
    const int tprev = (tt == 0) ? 1 : tt - 1;
    const int tnext = (tt == Tv - 1) ? Tv - 2 : tt + 1;

    const int t = threadIdx.x;
    const int lane = t & 31;
    const int w = t >> 5;
    const int gid = lane >> 2, tig = lane & 3;
    const int wm = w >> 2, wn = w & 3;

    const int lrow = t >> 2;
    const int dc = (t & 3) * 16;
    const int cstL = (t & 3) << 3;
    const int kp0 = dc >> 1;

    const int vp = t >> 3;
    const int vd = (t & 7) * 4;

    {
        const unsigned* qb = (const unsigned*)g_qh +
            (size_t)(b * TNv + tt * Nv + nb * 64 + lrow) * CW + hh * 32 + kp0;
        uint4 u0 = *(const uint4*)qb;
        uint4 u1 = *(const uint4*)(qb + 4);
        const int cq = lrow ^ cstL;
        unsigned* Kq = usm + AKS1;
        Kq[(kp0 + 0) * 72 + cq] = u0.x;
        Kq[(kp0 + 1) * 72 + cq] = u0.y;
        Kq[(kp0 + 2) * 72 + cq] = u0.z;
        Kq[(kp0 + 3) * 72 + cq] = u0.w;
        Kq[(kp0 + 4) * 72 + cq] = u1.x;
        Kq[(kp0 + 5) * 72 + cq] = u1.y;
        Kq[(kp0 + 6) * 72 + cq] = u1.z;
        Kq[(kp0 + 7) * 72 + cq] = u1.w;
    }
    uint4 ku0, ku1;
    uint2 vA0, vB0, vA1, vB1;
    {
        const size_t tokbase = (size_t)(b * TNv + tprev * Nv);
        const unsigned* kb_ = (const unsigned*)g_kh +
            (tokbase + lrow) * CW + hh * 32 + kp0;
        ku0 = *(const uint4*)kb_;
        ku1 = *(const uint4*)(kb_ + 4);
        const unsigned* va = (const unsigned*)g_vh +
            (tokbase + 2 * vp) * CW + hh * 32 + (vd >> 1);
        const unsigned* vb2 = va + CW;
        vA0 = *(const uint2*)va;  vB0 = *(const uint2*)vb2;
        vA1 = *(const uint2*)(va + 16); vB1 = *(const uint2*)(vb2 + 16);
        const int ck = lrow ^ cstL;
        unsigned* K0 = usm + AKS0;
        K0[(kp0 + 0) * 72 + ck] = ku0.x;
        K0[(kp0 + 1) * 72 + ck] = ku0.y;
        K0[(kp0 + 2) * 72 + ck] = ku0.z;
        K0[(kp0 + 3) * 72 + ck] = ku0.w;
        K0[(kp0 + 4) * 72 + ck] = ku1.x;
        K0[(kp0 + 5) * 72 + ck] = ku1.y;
        K0[(kp0 + 6) * 72 + ck] = ku1.z;
        K0[(kp0 + 7) * 72 + ck] = ku1.w;
        unsigned* vr = usm + AVS0 + vp * 72 + vd;
        vr[0] = h2lows(vA0.x, vB0.x);
        vr[1] = h2highs(vA0.x, vB0.x);
        vr[2] = h2lows(vA0.y, vB0.y);
        vr[3] = h2highs(vA0.y, vB0.y);
        vr[32] = h2lows(vA1.x, vB1.x);
        vr[33] = h2highs(vA1.x, vB1.x);
        vr[34] = h2lows(vA1.y, vB1.y);
        vr[35] = h2highs(vA1.y, vB1.y);
    }
    if (t < 64) { Mrow[t] = -1e30f; Lrow[t] = 0.0f; }
    __syncthreads();

    unsigned qa[4][2][4];
#pragma unroll
    for (int st = 0; st < 4; st++) {
        const int cs = (st & 3) << 3;
        const int kr0 = (st * 8 + tig) * 72;
        const int kr1 = (st * 8 + tig + 4) * 72;
        const unsigned* Kq = usm + AKS1;
#pragma unroll
        for (int mi = 0; mi < 2; mi++) {
            int q0 = wm * 32 + mi * 16 + gid;
            qa[st][mi][0] = Kq[kr0 + (q0 ^ cs)];
            qa[st][mi][1] = Kq[kr0 + ((q0 + 8) ^ cs)];
            qa[st][mi][2] = Kq[kr1 + (q0 ^ cs)];
            qa[st][mi][3] = Kq[kr1 + ((q0 + 8) ^ cs)];
        }
    }

    float o[2][2][4];
#pragma unroll
    for (int mi = 0; mi < 2; mi++)
#pragma unroll
        for (int nj = 0; nj < 2; nj++)
#pragma unroll
            for (int r = 0; r < 4; r++) o[mi][nj][r] = 0.0f;

    for (int kt = 0; kt < 18; kt++) {
        const int cb = (kt & 1) ? AKS1 : AKS0;
        const unsigned* Kc = usm + cb;
        const unsigned* Vc = usm + cb + 2304;

        if (kt + 1 < 18) {
            const int kt2 = kt + 1;
            const int tsrc = (kt2 < 9) ? tprev : tnext;
            const int nk0 = (kt2 % 9) * 64;
            const size_t tokbase = (size_t)(b * TNv + tsrc * Nv + nk0);
            const unsigned* kb_ = (const unsigned*)g_kh +
                (tokbase + lrow) * CW + hh * 32 + kp0;
            ku0 = *(const uint4*)kb_;
            ku1 = *(const uint4*)(kb_ + 4);
            const unsigned* va = (const unsigned*)g_vh +
                (tokbase + 2 * vp) * CW + hh * 32 + (vd >> 1);
            const unsigned* vb2 = va + CW;
            vA0 = *(const uint2*)va;  vB0 = *(const uint2*)vb2;
            vA1 = *(const uint2*)(va + 16); vB1 = *(const uint2*)(vb2 + 16);
        }

        float s[2][2][4];
#pragma unroll
        for (int mi = 0; mi < 2; mi++)
#pragma unroll
            for (int ni = 0; ni < 2; ni++)
#pragma unroll
                for (int r = 0; r < 4; r++) s[mi][ni][r] = 0.0f;
#pragma unroll
        for (int st = 0; st < 4; st++) {
            const int cs = (st & 3) << 3;
            const int kr0 = (st * 8 + tig) * 72;
            const int kr1 = (st * 8 + tig + 4) * 72;
            unsigned bb[2][2];
#pragma unroll
            for (int ni = 0; ni < 2; ni++) {
                int kc = wn * 16 + ni * 8 + gid;
                bb[ni][0] = Kc[kr0 + (kc ^ cs)];
                bb[ni][1] = Kc[kr1 + (kc ^ cs)];
            }
#pragma unroll
            for (int mi = 0; mi < 2; mi++)
#pragma unroll
                for (int ni = 0; ni < 2; ni++)
                    mma16(s[mi][ni], qa[st][mi], bb[ni]);
        }

#pragma unroll
        for (int mi = 0; mi < 2; mi++)
#pragma unroll
            for (int h2 = 0; h2 < 2; h2++) {
                float mx = fmaxf(fmaxf(s[mi][0][h2 * 2], s[mi][0][h2 * 2 + 1]),
                                 fmaxf(s[mi][1][h2 * 2], s[mi][1][h2 * 2 + 1]));
                mx = fmaxf(mx, __shfl_xor_sync(0xffffffffu, mx, 1));
                mx = fmaxf(mx, __shfl_xor_sync(0xffffffffu, mx, 2));
                if (tig == 0)
                    red[wn * 64 + wm * 32 + mi * 16 + h2 * 8 + gid] = mx;
            }
        __syncthreads();
        if (t < 64) {
            float tm = fmaxf(fmaxf(red[t], red[64 + t]),
                             fmaxf(red[128 + t], red[192 + t]));
            float mold = Mrow[t];
            float mnew = fmaxf(mold, tm);
            Mrow[t] = mnew;
            Arow[t] = __expf(mold - mnew);
        }
        __syncthreads();

        if (kt + 1 < 18) {
            const int nbuf = cb ^ AKS1;
            unsigned* Kn = usm + nbuf;
            const int ck = lrow ^ cstL;
            Kn[(kp0 + 0) * 72 + ck] = ku0.x;
            Kn[(kp0 + 1) * 72 + ck] = ku0.y;
            Kn[(kp0 + 2) * 72 + ck] = ku0.z;
            Kn[(kp0 + 3) * 72 + ck] = ku0.w;
            Kn[(kp0 + 4) * 72 + ck] = ku1.x;
            Kn[(kp0 + 5) * 72 + ck] = ku1.y;
            Kn[(kp0 + 6) * 72 + ck] = ku1.z;
            Kn[(kp0 + 7) * 72 + ck] = ku1.w;
            unsigned* vr = usm + nbuf + 2304 + vp * 72 + vd;
            vr[0] = h2lows(vA0.x, vB0.x);
            vr[1] = h2highs(vA0.x, vB0.x);
            vr[2] = h2lows(vA0.y, vB0.y);
            vr[3] = h2highs(vA0.y, vB0.y);
            vr[32] = h2lows(vA1.x, vB1.x);
            vr[33] = h2highs(vA1.x, vB1.x);
            vr[34] = h2lows(vA1.y, vB1.y);
            vr[35] = h2highs(vA1.y, vB1.y);
        }

        const int cp = wn << 3;
        const int kp1 = wn * 8 + tig;
        const int kp2 = kp1 + 4;
#pragma unroll
        for (int mi = 0; mi < 2; mi++)
#pragma unroll
            for (int h2 = 0; h2 < 2; h2++) {
                int r = wm * 32 + mi * 16 + h2 * 8 + gid;
                float mrow = Mrow[r];
                float al = Arow[r];
                float p0 = __expf(s[mi][0][h2 * 2]     - mrow);
                float p1 = __expf(s[mi][0][h2 * 2 + 1] - mrow);
                float p2 = __expf(s[mi][1][h2 * 2]     - mrow);
                float p3 = __expf(s[mi][1][h2 * 2 + 1] - mrow);
                float rs = p0 + p1 + p2 + p3;
                rs += __shfl_xor_sync(0xffffffffu, rs, 1);
                rs += __shfl_xor_sync(0xffffffffu, rs, 2);
                if (tig == 0) red[wn * 64 + r] = rs;
                int rq = r ^ cp;
                Ps[kp1 * 72 + rq] = f2h2(p0, p1);
                Ps[kp2 * 72 + rq] = f2h2(p2, p3);
                o[mi][0][h2 * 2]     *= al;
                o[mi][0][h2 * 2 + 1] *= al;
                o[mi][1][h2 * 2]     *= al;
                o[mi][1][h2 * 2 + 1] *= al;
            }
        __syncthreads();
        if (t < 64)
            Lrow[t] = Lrow[t] * Arow[t] +
                      red[t] + red[64 + t] + red[128 + t] + red[192 + t];

#pragma unroll
        for (int st = 0; st < 4; st++) {
            const int cs = (st & 3) << 3;
            const int kr0 = (st * 8 + tig) * 72;
            const int kr1 = (st * 8 + tig + 4) * 72;
            unsigned a[2][4], bb[2][2];
#pragma unroll
            for (int mi = 0; mi < 2; mi++) {
                int q0 = wm * 32 + mi * 16 + gid;
                a[mi][0] = Ps[kr0 + (q0 ^ cs)];
                a[mi][1] = Ps[kr0 + ((q0 + 8) ^ cs)];
                a[mi][2] = Ps[kr1 + (q0 ^ cs)];
                a[mi][3] = Ps[kr1 + ((q0 + 8) ^ cs)];
            }
#pragma unroll
            for (int nj = 0; nj < 2; nj++) {
                int dcol = wn * 16 + nj * 8 + gid;
                bb[nj][0] = Vc[kr0 + dcol];
                bb[nj][1] = Vc[kr1 + dcol];
            }
#pragma unroll
            for (int mi = 0; mi < 2; mi++)
#pragma unroll
                for (int nj = 0; nj < 2; nj++)
                    mma16(o[mi][nj], a[mi], bb[nj]);
        }
    }

    __syncthreads();
#pragma unroll
    for (int mi = 0; mi < 2; mi++)
#pragma unroll
        for (int h2 = 0; h2 < 2; h2++) {
            int r = wm * 32 + mi * 16 + h2 * 8 + gid;
            float inv = 1.0f / Lrow[r];
            size_t token = (size_t)(b * TNv + tt * Nv + nb * 64 + r);
            __half* ob = g_oh + token * Cv + hh * HDv;
#pragma unroll
            for (int nj = 0; nj < 2; nj++) {
                int dcol = wn * 16 + nj * 8 + tig * 2;
                *(unsigned*)(ob + dcol) =
                    f2h2(o[mi][nj][h2 * 2] * inv, o[mi][nj][h2 * 2 + 1] * inv);
            }
        }
}

// ---------------------------------------------------------------------------
// Launch
// ---------------------------------------------------------------------------
extern "C" void kernel_launch(void* const* d_in, const int* in_sizes, int n_in,
                              void* d_out, int out_size)
{
    (void)in_sizes; (void)n_in; (void)out_size;
    const float* img  = (const float*)d_in[0];
    const float* fcos = (const float*)d_in[1];
    const float* fsin = (const float*)d_in[2];
    const float* Wq   = (const float*)d_in[3];
    const float* Wk   = (const float*)d_in[4];
    const float* Wv   = (const float*)d_in[5];
    const float* Wo   = (const float*)d_in[6];
    const float* bo   = (const float*)d_in[7];
    float* out = (float*)d_out;

    __half *qh, *kh, *vh, *oh, *imgh, *wqh, *wkh, *wvh, *woh;
    cudaGetSymbolAddress((void**)&qh, g_qh);
    cudaGetSymbolAddress((void**)&kh, g_kh);
    cudaGetSymbolAddress((void**)&vh, g_vh);
    cudaGetSymbolAddress((void**)&oh, g_oh);
    cudaGetSymbolAddress((void**)&imgh, g_imgh);
    cudaGetSymbolAddress((void**)&wqh, g_wqh);
    cudaGetSymbolAddress((void**)&wkh, g_wkh);
    cudaGetSymbolAddress((void**)&wvh, g_wvh);
    cudaGetSymbolAddress((void**)&woh, g_woh);

    cudaFuncSetAttribute(attn_fp16,
                         cudaFuncAttributeMaxDynamicSharedMemorySize,
                         ATTN_SMEM_WORDS * (int)sizeof(unsigned));

    cvt_all<<<(TOT8 + 255) / 256, 256>>>(img, Wq, Wk, Wv, Wo);

    dim3 gblk(512);
    dim3 ggrid(Cv / 128, Mrows / 128);   // (8, 72)

    gemm_proj<<<ggrid, gblk>>>(imgh, wqh, qh, fcos, fsin, 0.125f);
    gemm_proj<<<ggrid, gblk>>>(imgh, wkh, kh, fcos, fsin, 1.0f);
    gemm_proj<<<ggrid, gblk>>>(imgh, wvh, vh, nullptr, nullptr, 1.0f);

    attn_fp16<<<Bv * Hv * Tv * 9, 256,
                ATTN_SMEM_WORDS * sizeof(unsigned)>>>();

    gemm_out<<<ggrid, gblk>>>(oh, woh, out, bo);
}

// round 17
// speedup vs baseline: 1.1047x; 1.1047x over previous
#include <cuda_runtime.h>
#include <cuda_fp16.h>
#include <math.h>
#include <stdint.h>

// Problem constants
#define Bv 2
#define Tv 8
#define Nv 576
#define Cv 1024
#define Hv 16
#define HDv 64
#define TNv (Tv * Nv)       // 4608
#define Mrows (Bv * TNv)    // 9216
#define CW (Cv / 2)         // 512 uint words per token row

// Scratch (device globals — no runtime allocation allowed)
__device__ __half g_qh[(size_t)Mrows * Cv];
__device__ __half g_kh[(size_t)Mrows * Cv];
__device__ __half g_vh[(size_t)Mrows * Cv];
__device__ __half g_oh[(size_t)Mrows * Cv];
__device__ __half g_imgh[(size_t)Mrows * Cv];
__device__ __half g_wqh[(size_t)Cv * Cv];
__device__ __half g_wkh[(size_t)Cv * Cv];
__device__ __half g_wvh[(size_t)Cv * Cv];
__device__ __half g_woh[(size_t)Cv * Cv];

// ---------------------------------------------------------------------------
// helpers
// ---------------------------------------------------------------------------
__device__ __forceinline__ unsigned f2h2(float lo, float hi) {
    __half2 h = __floats2half2_rn(lo, hi);
    return *(unsigned*)&h;
}
__device__ __forceinline__ unsigned h2lows(unsigned a, unsigned b) {
    unsigned r;
    asm("prmt.b32 %0, %1, %2, 0x5410;" : "=r"(r) : "r"(a), "r"(b));
    return r;
}
__device__ __forceinline__ unsigned h2highs(unsigned a, unsigned b) {
    unsigned r;
    asm("prmt.b32 %0, %1, %2, 0x7632;" : "=r"(r) : "r"(a), "r"(b));
    return r;
}
__device__ __forceinline__ void mma16(float d[4], const unsigned a[4],
                                      const unsigned b[2]) {
    asm volatile(
        "mma.sync.aligned.m16n8k16.row.col.f32.f16.f16.f32 "
        "{%0,%1,%2,%3},{%4,%5,%6,%7},{%8,%9},{%0,%1,%2,%3};"
        : "+f"(d[0]), "+f"(d[1]), "+f"(d[2]), "+f"(d[3])
        : "r"(a[0]), "r"(a[1]), "r"(a[2]), "r"(a[3]), "r"(b[0]), "r"(b[1]));
}
__device__ __forceinline__ uint32_t smem_u32(const void* p) {
    uint32_t a;
    asm("{ .reg .u64 t; cvta.to.shared.u64 t, %1; cvt.u32.u64 %0, t; }"
        : "=r"(a) : "l"(p));
    return a;
}
__device__ __forceinline__ void ldsm4(unsigned& r0, unsigned& r1,
                                      unsigned& r2, unsigned& r3,
                                      uint32_t addr) {
    asm volatile(
        "ldmatrix.sync.aligned.m8n8.x4.shared.b16 {%0,%1,%2,%3}, [%4];"
        : "=r"(r0), "=r"(r1), "=r"(r2), "=r"(r3) : "r"(addr));
}

// ---------------------------------------------------------------------------
// Merged fp32 -> fp16 conversion pre-pass (img + 4 weights), 8 elems/thread
// ---------------------------------------------------------------------------
#define IMG8 ((int)((size_t)Mrows * Cv / 8))   // 1179648
#define W8   ((int)((size_t)Cv * Cv / 8))      // 131072
#define TOT8 (IMG8 + 4 * W8)                   // 1703936

__global__ __launch_bounds__(256) void cvt_all(
    const float* __restrict__ img, const float* __restrict__ wq,
    const float* __restrict__ wk, const float* __restrict__ wv,
    const float* __restrict__ wo)
{
    int i = blockIdx.x * blockDim.x + threadIdx.x;
    if (i >= TOT8) return;
    const float* s;
    __half* d;
    if (i < IMG8) {
        s = img + (size_t)i * 8;
        d = g_imgh + (size_t)i * 8;
    } else {
        int j = i - IMG8;
        int wsel = j / W8, r = j % W8;
        const float* ws = (wsel == 0) ? wq : (wsel == 1) ? wk
                         : (wsel == 2) ? wv : wo;
        __half* wd = (wsel == 0) ? g_wqh : (wsel == 1) ? g_wkh
                    : (wsel == 2) ? g_wvh : g_woh;
        s = ws + (size_t)r * 8;
        d = wd + (size_t)r * 8;
    }
    const float4* sp = (const float4*)s;
    float4 a = sp[0], b2 = sp[1];
    uint4 o;
    o.x = f2h2(a.x, a.y);  o.y = f2h2(a.z, a.w);
    o.z = f2h2(b2.x, b2.y); o.w = f2h2(b2.z, b2.w);
    *(uint4*)d = o;
}

// ---------------------------------------------------------------------------
// Projection GEMM (A half, W half): out = half( rope?( scale * A@W^T ) )
// 256 threads, single-buffered, ROW-MAJOR smem [row][k] (16 words/row),
// swizzle group' = g ^ ((row>>1)&3); fragments via ldmatrix.x4 (round-15
// champion). __launch_bounds__(256, 2) caps regs at 128 -> 2 CTAs/SM,
// 16 resident warps while keeping the fat 64x32 warp tile (LDSM:mma 0.375).
// ---------------------------------------------------------------------------
__global__ __launch_bounds__(256, 2) void gemm_proj(
    const __half* __restrict__ Ah, const __half* __restrict__ Wh,
    __half* __restrict__ Out,
    const float* __restrict__ fcos, const float* __restrict__ fsin,
    float scale)
{
    __shared__ unsigned As[128 * 16];
    __shared__ unsigned Bs[128 * 16];

    const int t = threadIdx.x;
    const int lane = t & 31;
    const int w = t >> 5;
    const int gid = lane >> 2, tig = lane & 3;
    const int wm = (w >> 2) * 64, wn = (w & 3) * 32;
    const int m0 = blockIdx.y * 128, n0 = blockIdx.x * 128;

    // loader: rows row0, row0+64; 16B group kg within the 16-word chunk row
    const int row0 = t >> 2;
    const int kg = t & 3;
    const unsigned* Ap0 = (const unsigned*)Ah + (size_t)(m0 + row0) * CW + kg * 4;
    const unsigned* Ap1 = (const unsigned*)Ah + (size_t)(m0 + 64 + row0) * CW + kg * 4;
    const unsigned* Wp0 = (const unsigned*)Wh + (size_t)(n0 + row0) * CW + kg * 4;
    const unsigned* Wp1 = (const unsigned*)Wh + (size_t)(n0 + 64 + row0) * CW + kg * 4;

    // STS offsets (row0+64 keeps the same swizzle: +64 doesn't change (r>>1)&3)
    const int sw0 = kg ^ ((row0 >> 1) & 3);
    const int sts0 = row0 * 16 + sw0 * 4;
    const int sts1 = (row0 + 64) * 16 + sw0 * 4;

    // LDSM per-lane bases (loop-invariant)
    const uint32_t sbA = smem_u32(As), sbB = smem_u32(Bs);
    const int aRowL = ((lane >> 3) & 1) * 8 + (lane & 7);
    const int aKsel = lane >> 4;              // 0/1
    const int bRowL = (lane >> 4) * 8 + (lane & 7);
    const int bKsel = (lane >> 3) & 1;
    uint32_t baseA[4]; int swzA[4];
#pragma unroll
    for (int mt = 0; mt < 4; mt++) {
        int r = wm + mt * 16 + aRowL;
        baseA[mt] = sbA + (uint32_t)(r * 16) * 4;
        swzA[mt] = (r >> 1) & 3;
    }
    uint32_t baseB[2]; int swzB[2];
#pragma unroll
    for (int np = 0; np < 2; np++) {
        int r = wn + np * 16 + bRowL;
        baseB[np] = sbB + (uint32_t)(r * 16) * 4;
        swzB[np] = (r >> 1) & 3;
    }

    float acc[4][4][4];
#pragma unroll
    for (int mt = 0; mt < 4; mt++)
#pragma unroll
        for (int nt = 0; nt < 4; nt++)
#pragma unroll
            for (int r = 0; r < 4; r++) acc[mt][nt][r] = 0.0f;

    uint4 xa = *(const uint4*)Ap0;
    uint4 ya = *(const uint4*)Ap1;
    uint4 za = *(const uint4*)Wp0;
    uint4 ua = *(const uint4*)Wp1;

    for (int ch = 0; ch < 32; ch++) {
        __syncthreads();
        *(uint4*)(As + sts0) = xa;
        *(uint4*)(As + sts1) = ya;
        *(uint4*)(Bs + sts0) = za;
        *(uint4*)(Bs + sts1) = ua;
        __syncthreads();
        if (ch + 1 < 32) {
            const int kc = (ch + 1) * 16;
            xa = *(const uint4*)(Ap0 + kc);
            ya = *(const uint4*)(Ap1 + kc);
            za = *(const uint4*)(Wp0 + kc);
            ua = *(const uint4*)(Wp1 + kc);
        }
#pragma unroll
        for (int s = 0; s < 2; s++) {
            unsigned a[4][4], bb[4][2];
            const int gA = s * 2 + aKsel;
            const int gB = s * 2 + bKsel;
#pragma unroll
            for (int mt = 0; mt < 4; mt++)
                ldsm4(a[mt][0], a[mt][1], a[mt][2], a[mt][3],
                      baseA[mt] + (uint32_t)((gA ^ swzA[mt]) << 4));
#pragma unroll
            for (int np = 0; np < 2; np++) {
                unsigned r0, r1, r2, r3;
                ldsm4(r0, r1, r2, r3,
                      baseB[np] + (uint32_t)((gB ^ swzB[np]) << 4));
                bb[2 * np][0] = r0;  bb[2 * np][1] = r1;
                bb[2 * np + 1][0] = r2;  bb[2 * np + 1][1] = r3;
            }
#pragma unroll
            for (int mt = 0; mt < 4; mt++)
#pragma unroll
                for (int nt = 0; nt < 4; nt++)
                    mma16(acc[mt][nt], a[mt], bb[nt]);
        }
    }

    const bool rope = (fcos != nullptr);
#pragma unroll
    for (int mt = 0; mt < 4; mt++) {
        const int r = m0 + wm + mt * 16 + gid;
        const int r8 = r + 8;
        const int s_lo = (r  >= TNv) ? r  - TNv : r;
        const int s_hi = (r8 >= TNv) ? r8 - TNv : r8;
#pragma unroll
        for (int nt = 0; nt < 4; nt++) {
            const int c = n0 + wn + nt * 8 + tig * 2;
            float a0 = acc[mt][nt][0] * scale;
            float a1 = acc[mt][nt][1] * scale;
            float a2 = acc[mt][nt][2] * scale;
            float a3 = acc[mt][nt][3] * scale;
            if (rope) {
                const int d = c & 63;
                float2 cl = *(const float2*)(fcos + (size_t)s_lo * HDv + d);
                float2 sl = *(const float2*)(fsin + (size_t)s_lo * HDv + d);
                float2 chh = *(const float2*)(fcos + (size_t)s_hi * HDv + d);
                float2 sh = *(const float2*)(fsin + (size_t)s_hi * HDv + d);
                float y0 = a0 * cl.x - a1 * sl.x;
                float y1 = a1 * cl.y + a0 * sl.y;
                float y2 = a2 * chh.x - a3 * sh.x;
                float y3 = a3 * chh.y + a2 * sh.y;
                a0 = y0; a1 = y1; a2 = y2; a3 = y3;
            }
            *(unsigned*)(Out + (size_t)r  * Cv + c) = f2h2(a0, a1);
            *(unsigned*)(Out + (size_t)r8 * Cv + c) = f2h2(a2, a3);
        }
    }
}

// ---------------------------------------------------------------------------
// Output GEMM (A half, W half): out fp32 = A@W^T + bias. Same LDSM scheme,
// same (256, 2) register cap.
// ---------------------------------------------------------------------------
__global__ __launch_bounds__(256, 2) void gemm_out(
    const __half* __restrict__ Ah, const __half* __restrict__ Wh,
    float* __restrict__ Cout, const float* __restrict__ bias)
{
    __shared__ unsigned As[128 * 16];
    __shared__ unsigned Bs[128 * 16];

    const int t = threadIdx.x;
    const int lane = t & 31;
    const int w = t >> 5;
    const int gid = lane >> 2, tig = lane & 3;
    const int wm = (w >> 2) * 64, wn = (w & 3) * 32;
    const int m0 = blockIdx.y * 128, n0 = blockIdx.x * 128;

    const int row0 = t >> 2;
    const int kg = t & 3;
    const unsigned* Ap0 = (const unsigned*)Ah + (size_t)(m0 + row0) * CW + kg * 4;
    const unsigned* Ap1 = (const unsigned*)Ah + (size_t)(m0 + 64 + row0) * CW + kg * 4;
    const unsigned* Wp0 = (const unsigned*)Wh + (size_t)(n0 + row0) * CW + kg * 4;
    const unsigned* Wp1 = (const unsigned*)Wh + (size_t)(n0 + 64 + row0) * CW + kg * 4;

    const int sw0 = kg ^ ((row0 >> 1) & 3);
    const int sts0 = row0 * 16 + sw0 * 4;
    const int sts1 = (row0 + 64) * 16 + sw0 * 4;

    const uint32_t sbA = smem_u32(As), sbB = smem_u32(Bs);
    const int aRowL = ((lane >> 3) & 1) * 8 + (lane & 7);
    const int aKsel = lane >> 4;
    const int bRowL = (lane >> 4) * 8 + (lane & 7);
    const int bKsel = (lane >> 3) & 1;
    uint32_t baseA[4]; int swzA[4];
#pragma unroll
    for (int mt = 0; mt < 4; mt++) {
        int r = wm + mt * 16 + aRowL;
        baseA[mt] = sbA + (uint32_t)(r * 16) * 4;
        swzA[mt] = (r >> 1) & 3;
    }
    uint32_t baseB[2]; int swzB[2];
#pragma unroll
    for (int np = 0; np < 2; np++) {
        int r = wn + np * 16 + bRowL;
        baseB[np] = sbB + (uint32_t)(r * 16) * 4;
        swzB[np] = (r >> 1) & 3;
    }

    float acc[4][4][4];
#pragma unroll
    for (int mt = 0; mt < 4; mt++)
#pragma unroll
        for (int nt = 0; nt < 4; nt++)
#pragma unroll
            for (int r = 0; r < 4; r++) acc[mt][nt][r] = 0.0f;

    uint4 xa = *(const uint4*)Ap0;
    uint4 ya = *(const uint4*)Ap1;
    uint4 za = *(const uint4*)Wp0;
    uint4 ua = *(const uint4*)Wp1;

    for (int ch = 0; ch < 32; ch++) {
        __syncthreads();
        *(uint4*)(As + sts0) = xa;
        *(uint4*)(As + sts1) = ya;
        *(uint4*)(Bs + sts0) = za;
        *(uint4*)(Bs + sts1) = ua;
        __syncthreads();
        if (ch + 1 < 32) {
            const int kc = (ch + 1) * 16;
            xa = *(const uint4*)(Ap0 + kc);
            ya = *(const uint4*)(Ap1 + kc);
            za = *(const uint4*)(Wp0 + kc);
            ua = *(const uint4*)(Wp1 + kc);
        }
#pragma unroll
        for (int s = 0; s < 2; s++) {
            unsigned a[4][4], bb[4][2];
            const int gA = s * 2 + aKsel;
            const int gB = s * 2 + bKsel;
#pragma unroll
            for (int mt = 0; mt < 4; mt++)
                ldsm4(a[mt][0], a[mt][1], a[mt][2], a[mt][3],
                      baseA[mt] + (uint32_t)((gA ^ swzA[mt]) << 4));
#pragma unroll
            for (int np = 0; np < 2; np++) {
                unsigned r0, r1, r2, r3;
                ldsm4(r0, r1, r2, r3,
                      baseB[np] + (uint32_t)((gB ^ swzB[np]) << 4));
                bb[2 * np][0] = r0;  bb[2 * np][1] = r1;
                bb[2 * np + 1][0] = r2;  bb[2 * np + 1][1] = r3;
            }
#pragma unroll
            for (int mt = 0; mt < 4; mt++)
#pragma unroll
                for (int nt = 0; nt < 4; nt++)
                    mma16(acc[mt][nt], a[mt], bb[nt]);
        }
    }

#pragma unroll
    for (int mt = 0; mt < 4; mt++) {
        int r = m0 + wm + mt * 16 + gid;
#pragma unroll
        for (int nt = 0; nt < 4; nt++) {
            int c = n0 + wn + nt * 8 + tig * 2;
            float b0v = bias[c], b1v = bias[c + 1];
            float2 v0, v1;
            v0.x = acc[mt][nt][0] + b0v;
            v0.y = acc[mt][nt][1] + b1v;
            v1.x = acc[mt][nt][2] + b0v;
            v1.y = acc[mt][nt][3] + b1v;
            *(float2*)(Cout + (size_t)r * Cv + c) = v0;
            *(float2*)(Cout + (size_t)(r + 8) * Cv + c) = v1;
        }
    }
}

// ---------------------------------------------------------------------------
// Flash attention, fp16 (round-11/15 version, UNCHANGED).
// Buffer layout (uint words): [Ks0|Vs0|Ks1|Vs1|Ps|red|Mrow|Lrow|Arow]
// ---------------------------------------------------------------------------
#define AKS0 0
#define AVS0 2304
#define AKS1 4608
#define AVS1 6912
#define APS  9216
#define ARED 11520
#define AMR  11776
#define ALR  11840
#define AAR  11904
#define ATTN_SMEM_WORDS 11968

__global__ __launch_bounds__(256) void attn_fp16()
{
    extern __shared__ unsigned usm[];
    unsigned* Ps = usm + APS;
    float* red  = (float*)(usm + ARED);
    float* Mrow = (float*)(usm + AMR);
    float* Lrow = (float*)(usm + ALR);
    float* Arow = (float*)(usm + AAR);

    const int bx = blockIdx.x;
    const int nb = bx % 9;
    const int tt = (bx / 9) % Tv;
    const int hh = (bx / (9 * Tv)) % Hv;
    const int b  = bx / (9 * Tv * Hv);
    const int tprev = (tt == 0) ? 1 : tt - 1;
    const int tnext = (tt == Tv - 1) ? Tv - 2 : tt + 1;

    const int t = threadIdx.x;
    const int lane = t & 31;
    const int w = t >> 5;
    const int gid = lane >> 2, tig = lane & 3;
    const int wm = w >> 2, wn = w & 3;

    const int lrow = t >> 2;
    const int dc = (t & 3) * 16;
    const int cstL = (t & 3) << 3;
    const int kp0 = dc >> 1;

    const int vp = t >> 3;
    const int vd = (t & 7) * 4;

    {
        const unsigned* qb = (const unsigned*)g_qh +
            (size_t)(b * TNv + tt * Nv + nb * 64 + lrow) * CW + hh * 32 + kp0;
        uint4 u0 = *(const uint4*)qb;
        uint4 u1 = *(const uint4*)(qb + 4);
        const int cq = lrow ^ cstL;
        unsigned* Kq = usm + AKS1;
        Kq[(kp0 + 0) * 72 + cq] = u0.x;
        Kq[(kp0 + 1) * 72 + cq] = u0.y;
        Kq[(kp0 + 2) * 72 + cq] = u0.z;
        Kq[(kp0 + 3) * 72 + cq] = u0.w;
        Kq[(kp0 + 4) * 72 + cq] = u1.x;
        Kq[(kp0 + 5) * 72 + cq] = u1.y;
        Kq[(kp0 + 6) * 72 + cq] = u1.z;
        Kq[(kp0 + 7) * 72 + cq] = u1.w;
    }
    uint4 ku0, ku1;
    uint2 vA0, vB0, vA1, vB1;
    {
        const size_t tokbase = (size_t)(b * TNv + tprev * Nv);
        const unsigned* kb_ = (const unsigned*)g_kh +
            (tokbase + lrow) * CW + hh * 32 + kp0;
        ku0 = *(const uint4*)kb_;
        ku1 = *(const uint4*)(kb_ + 4);
        const unsigned* va = (const unsigned*)g_vh +
            (tokbase + 2 * vp) * CW + hh * 32 + (vd >> 1);
        const unsigned* vb2 = va + CW;
        vA0 = *(const uint2*)va;  vB0 = *(const uint2*)vb2;
        vA1 = *(const uint2*)(va + 16); vB1 = *(const uint2*)(vb2 + 16);
        const int ck = lrow ^ cstL;
        unsigned* K0 = usm + AKS0;
        K0[(kp0 + 0) * 72 + ck] = ku0.x;
        K0[(kp0 + 1) * 72 + ck] = ku0.y;
        K0[(kp0 + 2) * 72 + ck] = ku0.z;
        K0[(kp0 + 3) * 72 + ck] = ku0.w;
        K0[(kp0 + 4) * 72 + ck] = ku1.x;
        K0[(kp0 + 5) * 72 + ck] = ku1.y;
        K0[(kp0 + 6) * 72 + ck] = ku1.z;
        K0[(kp0 + 7) * 72 + ck] = ku1.w;
        unsigned* vr = usm + AVS0 + vp * 72 + vd;
        vr[0] = h2lows(vA0.x, vB0.x);
        vr[1] = h2highs(vA0.x, vB0.x);
        vr[2] = h2lows(vA0.y, vB0.y);
        vr[3] = h2highs(vA0.y, vB0.y);
        vr[32] = h2lows(vA1.x, vB1.x);
        vr[33] = h2highs(vA1.x, vB1.x);
        vr[34] = h2lows(vA1.y, vB1.y);
        vr[35] = h2highs(vA1.y, vB1.y);
    }
    if (t < 64) { Mrow[t] = -1e30f; Lrow[t] = 0.0f; }
    __syncthreads();

    unsigned qa[4][2][4];
#pragma unroll
    for (int st = 0; st < 4; st++) {
        const int cs = (st & 3) << 3;
        const int kr0 = (st * 8 + tig) * 72;
        const int kr1 = (st * 8 + tig + 4) * 72;
        const unsigned* Kq = usm + AKS1;
#pragma unroll
        for (int mi = 0; mi < 2; mi++) {
            int q0 = wm * 32 + mi * 16 + gid;
            qa[st][mi][0] = Kq[kr0 + (q0 ^ cs)];
            qa[st][mi][1] = Kq[kr0 + ((q0 + 8) ^ cs)];
            qa[st][mi][2] = Kq[kr1 + (q0 ^ cs)];
            qa[st][mi][3] = Kq[kr1 + ((q0 + 8) ^ cs)];
        }
    }

    float o[2][2][4];
#pragma unroll
    for (int mi = 0; mi < 2; mi++)
#pragma unroll
        for (int nj = 0; nj < 2; nj++)
#pragma unroll
            for (int r = 0; r < 4; r++) o[mi][nj][r] = 0.0f;

    for (int kt = 0; kt < 18; kt++) {
        const int cb = (kt & 1) ? AKS1 : AKS0;
        const unsigned* Kc = usm + cb;
        const unsigned* Vc = usm + cb + 2304;

        if (kt + 1 < 18) {
            const int kt2 = kt + 1;
            const int tsrc = (kt2 < 9) ? tprev : tnext;
            const int nk0 = (kt2 % 9) * 64;
            const size_t tokbase = (size_t)(b * TNv + tsrc * Nv + nk0);
            const unsigned* kb_ = (const unsigned*)g_kh +
                (tokbase + lrow) * CW + hh * 32 + kp0;
            ku0 = *(const uint4*)kb_;
            ku1 = *(const uint4*)(kb_ + 4);
            const unsigned* va = (const unsigned*)g_vh +
                (tokbase + 2 * vp) * CW + hh * 32 + (vd >> 1);
            const unsigned* vb2 = va + CW;
            vA0 = *(const uint2*)va;  vB0 = *(const uint2*)vb2;
            vA1 = *(const uint2*)(va + 16); vB1 = *(const uint2*)(vb2 + 16);
        }

        float s[2][2][4];
#pragma unroll
        for (int mi = 0; mi < 2; mi++)
#pragma unroll
            for (int ni = 0; ni < 2; ni++)
#pragma unroll
                for (int r = 0; r < 4; r++) s[mi][ni][r] = 0.0f;
#pragma unroll
        for (int st = 0; st < 4; st++) {
            const int cs = (st & 3) << 3;
            const int kr0 = (st * 8 + tig) * 72;
            const int kr1 = (st * 8 + tig + 4) * 72;
            unsigned bb[2][2];
#pragma unroll
            for (int ni = 0; ni < 2; ni++) {
                int kc = wn * 16 + ni * 8 + gid;
                bb[ni][0] = Kc[kr0 + (kc ^ cs)];
                bb[ni][1] = Kc[kr1 + (kc ^ cs)];
            }
#pragma unroll
            for (int mi = 0; mi < 2; mi++)
#pragma unroll
                for (int ni = 0; ni < 2; ni++)
                    mma16(s[mi][ni], qa[st][mi], bb[ni]);
        }

#pragma unroll
        for (int mi = 0; mi < 2; mi++)
#pragma unroll
            for (int h2 = 0; h2 < 2; h2++) {
                float mx = fmaxf(fmaxf(s[mi][0][h2 * 2], s[mi][0][h2 * 2 + 1]),
                                 fmaxf(s[mi][1][h2 * 2], s[mi][1][h2 * 2 + 1]));
                mx = fmaxf(mx, __shfl_xor_sync(0xffffffffu, mx, 1));
                mx = fmaxf(mx, __shfl_xor_sync(0xffffffffu, mx, 2));
                if (tig == 0)
                    red[wn * 64 + wm * 32 + mi * 16 + h2 * 8 + gid] = mx;
            }
        __syncthreads();
        if (t < 64) {
            float tm = fmaxf(fmaxf(red[t], red[64 + t]),
                             fmaxf(red[128 + t], red[192 + t]));
            float mold = Mrow[t];
            float mnew = fmaxf(mold, tm);
            Mrow[t] = mnew;
            Arow[t] = __expf(mold - mnew);
        }
        __syncthreads();

        if (kt + 1 < 18) {
            const int nbuf = cb ^ AKS1;
            unsigned* Kn = usm + nbuf;
            const int ck = lrow ^ cstL;
            Kn[(kp0 + 0) * 72 + ck] = ku0.x;
            Kn[(kp0 + 1) * 72 + ck] = ku0.y;
            Kn[(kp0 + 2) * 72 + ck] = ku0.z;
            Kn[(kp0 + 3) * 72 + ck] = ku0.w;
            Kn[(kp0 + 4) * 72 + ck] = ku1.x;
            Kn[(kp0 + 5) * 72 + ck] = ku1.y;
            Kn[(kp0 + 6) * 72 + ck] = ku1.z;
            Kn[(kp0 + 7) * 72 + ck] = ku1.w;
            unsigned* vr = usm + nbuf + 2304 + vp * 72 + vd;
            vr[0] = h2lows(vA0.x, vB0.x);
            vr[1] = h2highs(vA0.x, vB0.x);
            vr[2] = h2lows(vA0.y, vB0.y);
            vr[3] = h2highs(vA0.y, vB0.y);
            vr[32] = h2lows(vA1.x, vB1.x);
            vr[33] = h2highs(vA1.x, vB1.x);
            vr[34] = h2lows(vA1.y, vB1.y);
            vr[35] = h2highs(vA1.y, vB1.y);
        }

        const int cp = wn << 3;
        const int kp1 = wn * 8 + tig;
        const int kp2 = kp1 + 4;
#pragma unroll
        for (int mi = 0; mi < 2; mi++)
#pragma unroll
            for (int h2 = 0; h2 < 2; h2++) {
                int r = wm * 32 + mi * 16 + h2 * 8 + gid;
                float mrow = Mrow[r];
                float al = Arow[r];
                float p0 = __expf(s[mi][0][h2 * 2]     - mrow);
                float p1 = __expf(s[mi][0][h2 * 2 + 1] - mrow);
                float p2 = __expf(s[mi][1][h2 * 2]     - mrow);
                float p3 = __expf(s[mi][1][h2 * 2 + 1] - mrow);
                float rs = p0 + p1 + p2 + p3;
                rs += __shfl_xor_sync(0xffffffffu, rs, 1);
                rs += __shfl_xor_sync(0xffffffffu, rs, 2);
                if (tig == 0) red[wn * 64 + r] = rs;
                int rq = r ^ cp;
                Ps[kp1 * 72 + rq] = f2h2(p0, p1);
                Ps[kp2 * 72 + rq] = f2h2(p2, p3);
                o[mi][0][h2 * 2]     *= al;
                o[mi][0][h2 * 2 + 1] *= al;
                o[mi][1][h2 * 2]     *= al;
                o[mi][1][h2 * 2 + 1] *= al;
            }
        __syncthreads();
        if (t < 64)
            Lrow[t] = Lrow[t] * Arow[t] +
                      red[t] + red[64 + t] + red[128 + t] + red[192 + t];

#pragma unroll
        for (int st = 0; st < 4; st++) {
            const int cs = (st & 3) << 3;
            const int kr0 = (st * 8 + tig) * 72;
            const int kr1 = (st * 8 + tig + 4) * 72;
            unsigned a[2][4], bb[2][2];
#pragma unroll
            for (int mi = 0; mi < 2; mi++) {
                int q0 = wm * 32 + mi * 16 + gid;
                a[mi][0] = Ps[kr0 + (q0 ^ cs)];
                a[mi][1] = Ps[kr0 + ((q0 + 8) ^ cs)];
                a[mi][2] = Ps[kr1 + (q0 ^ cs)];
                a[mi][3] = Ps[kr1 + ((q0 + 8) ^ cs)];
            }
#pragma unroll
            for (int nj = 0; nj < 2; nj++) {
                int dcol = wn * 16 + nj * 8 + gid;
                bb[nj][0] = Vc[kr0 + dcol];
                bb[nj][1] = Vc[kr1 + dcol];
            }
#pragma unroll
            for (int mi = 0; mi < 2; mi++)
#pragma unroll
                for (int nj = 0; nj < 2; nj++)
                    mma16(o[mi][nj], a[mi], bb[nj]);
        }
    }

    __syncthreads();
#pragma unroll
    for (int mi = 0; mi < 2; mi++)
#pragma unroll
        for (int h2 = 0; h2 < 2; h2++) {
            int r = wm * 32 + mi * 16 + h2 * 8 + gid;
            float inv = 1.0f / Lrow[r];
            size_t token = (size_t)(b * TNv + tt * Nv + nb * 64 + r);
            __half* ob = g_oh + token * Cv + hh * HDv;
#pragma unroll
            for (int nj = 0; nj < 2; nj++) {
                int dcol = wn * 16 + nj * 8 + tig * 2;
                *(unsigned*)(ob + dcol) =
                    f2h2(o[mi][nj][h2 * 2] * inv, o[mi][nj][h2 * 2 + 1] * inv);
            }
        }
}

// ---------------------------------------------------------------------------
// Launch
// ---------------------------------------------------------------------------
extern "C" void kernel_launch(void* const* d_in, const int* in_sizes, int n_in,
                              void* d_out, int out_size)
{
    (void)in_sizes; (void)n_in; (void)out_size;
    const float* img  = (const float*)d_in[0];
    const float* fcos = (const float*)d_in[1];
    const float* fsin = (const float*)d_in[2];
    const float* Wq   = (const float*)d_in[3];
    const float* Wk   = (const float*)d_in[4];
    const float* Wv   = (const float*)d_in[5];
    const float* Wo   = (const float*)d_in[6];
    const float* bo   = (const float*)d_in[7];
    float* out = (float*)d_out;

    __half *qh, *kh, *vh, *oh, *imgh, *wqh, *wkh, *wvh, *woh;
    cudaGetSymbolAddress((void**)&qh, g_qh);
    cudaGetSymbolAddress((void**)&kh, g_kh);
    cudaGetSymbolAddress((void**)&vh, g_vh);
    cudaGetSymbolAddress((void**)&oh, g_oh);
    cudaGetSymbolAddress((void**)&imgh, g_imgh);
    cudaGetSymbolAddress((void**)&wqh, g_wqh);
    cudaGetSymbolAddress((void**)&wkh, g_wkh);
    cudaGetSymbolAddress((void**)&wvh, g_wvh);
    cudaGetSymbolAddress((void**)&woh, g_woh);

    cudaFuncSetAttribute(attn_fp16,
                         cudaFuncAttributeMaxDynamicSharedMemorySize,
                         ATTN_SMEM_WORDS * (int)sizeof(unsigned));

    cvt_all<<<(TOT8 + 255) / 256, 256>>>(img, Wq, Wk, Wv, Wo);

    dim3 gblk(256);
    dim3 ggrid(Cv / 128, Mrows / 128);   // (8, 72)

    gemm_proj<<<ggrid, gblk>>>(imgh, wqh, qh, fcos, fsin, 0.125f);
    gemm_proj<<<ggrid, gblk>>>(imgh, wkh, kh, fcos, fsin, 1.0f);
    gemm_proj<<<ggrid, gblk>>>(imgh, wvh, vh, nullptr, nullptr, 1.0f);

    attn_fp16<<<Bv * Hv * Tv * 9, 256,
                ATTN_SMEM_WORDS * sizeof(unsigned)>>>();

    gemm_out<<<ggrid, gblk>>>(oh, woh, out, bo);
}